// round 8
// baseline (speedup 1.0000x reference)
#include <cuda_runtime.h>
#include <cuda_fp16.h>

#define N_NODES 100000
#define E_EDGES 1600000
#define FIN 512
#define HC1 64
#define H1 8
#define C2 16
#define NEG_SLOPE 0.2f
#define SCAN_NB ((N_NODES + 1023) / 1024)

// ---------------- scratch (static __device__, allocation-free) ----------------
__device__ __half g_h1h [(size_t)N_NODES * HC1];   // fp16 h1 (only copy)
__device__ float  g_al1s[(size_t)N_NODES * H1];
__device__ float  g_al1d[(size_t)N_NODES * H1];
__device__ float  g_acc1[(size_t)N_NODES * HC1];   // NORMALIZED layer-1 aggregate
__device__ __half g_h2h [(size_t)N_NODES * C2];    // fp16 h2 for edge2 gather
__device__ float  g_al2s[(size_t)N_NODES];
__device__ float  g_al2d[(size_t)N_NODES];
__device__ float  g_acc2[(size_t)N_NODES * C2];    // NORMALIZED layer-2 aggregate
__device__ int    g_is64;

// CSR build scratch
__device__ int g_cnt      [N_NODES];
__device__ int g_incl     [N_NODES];
__device__ int g_part     [SCAN_NB + 1];
__device__ int g_row_start[N_NODES];
__device__ int g_row_end  [N_NODES];
__device__ int g_cursor   [N_NODES];
__device__ int g_csr_src  [E_EDGES];

__device__ __forceinline__ float leaky(float e) { return e > 0.f ? e : NEG_SLOPE * e; }

// m16n8k8 tf32 mma, row.col, f32 accumulate (operands: raw fp32 bits -> implicit tf32)
__device__ __forceinline__ void mma_tf32(float* d, const float* a, const float* b) {
    asm volatile(
        "mma.sync.aligned.m16n8k8.row.col.f32.tf32.tf32.f32 "
        "{%0,%1,%2,%3}, {%4,%5,%6,%7}, {%8,%9}, {%0,%1,%2,%3};\n"
        : "+f"(d[0]), "+f"(d[1]), "+f"(d[2]), "+f"(d[3])
        : "r"(__float_as_uint(a[0])), "r"(__float_as_uint(a[1])),
          "r"(__float_as_uint(a[2])), "r"(__float_as_uint(a[3])),
          "r"(__float_as_uint(b[0])), "r"(__float_as_uint(b[1])));
}

__device__ __forceinline__ void cp16(void* smem, const void* g) {
    unsigned s = (unsigned)__cvta_generic_to_shared(smem);
    asm volatile("cp.async.ca.shared.global [%0], [%1], 16;\n" :: "r"(s), "l"(g));
}
__device__ __forceinline__ void cp_commit() { asm volatile("cp.async.commit_group;\n"); }
template <int NN> __device__ __forceinline__ void cp_wait() {
    asm volatile("cp.async.wait_group %0;\n" :: "n"(NN));
}

// ---------------- edge dtype detection (int64 vs int32) ----------------
__global__ void detect_kernel(const int* __restrict__ ei_words) {
    __shared__ int nz;
    if (threadIdx.x == 0) nz = 0;
    __syncthreads();
    for (int i = threadIdx.x; i < 4096; i += blockDim.x)
        if (ei_words[2 * i + 1] != 0) nz = 1;
    __syncthreads();
    if (threadIdx.x == 0) g_is64 = (nz == 0);
}

__device__ __forceinline__ void load_edge(const void* ei, int gid, int& src, int& dst) {
    if (g_is64) {
        const long long* p = (const long long*)ei;
        src = (int)p[gid];
        dst = (int)p[E_EDGES + gid];
    } else {
        const int* p = (const int*)ei;
        src = p[gid];
        dst = p[E_EDGES + gid];
    }
}

__device__ __forceinline__ int load_dst(const void* ei, int gid) {
    if (g_is64) return (int)((const long long*)ei)[E_EDGES + gid];
    return ((const int*)ei)[E_EDGES + gid];
}

// ---------------- CSR build ----------------
__global__ void zero_kernel() {
    int i = blockIdx.x * blockDim.x + threadIdx.x;
    if (i < N_NODES) g_cnt[i] = 0;
}

__global__ void hist_kernel(const void* __restrict__ ei) {
    int gid = blockIdx.x * blockDim.x + threadIdx.x;
    if (gid >= E_EDGES) return;
    atomicAdd(&g_cnt[load_dst(ei, gid)], 1);
}

__global__ __launch_bounds__(1024) void scan1_kernel() {
    __shared__ int sm[1024];
    int i = blockIdx.x * 1024 + threadIdx.x;
    sm[threadIdx.x] = (i < N_NODES) ? g_cnt[i] : 0;
    __syncthreads();
#pragma unroll
    for (int off = 1; off < 1024; off <<= 1) {
        int t = (threadIdx.x >= off) ? sm[threadIdx.x - off] : 0;
        __syncthreads();
        sm[threadIdx.x] += t;
        __syncthreads();
    }
    if (i < N_NODES) g_incl[i] = sm[threadIdx.x];
    if (threadIdx.x == 1023) g_part[blockIdx.x] = sm[1023];
}

// warp-parallel exclusive scan of g_part (SCAN_NB entries), one warp
__global__ void scan2_kernel() {
    int lane = threadIdx.x;
    int run = 0;
    for (int b0 = 0; b0 < SCAN_NB; b0 += 32) {
        int idx = b0 + lane;
        int orig = (idx < SCAN_NB) ? g_part[idx] : 0;
        int v = orig;
#pragma unroll
        for (int off = 1; off < 32; off <<= 1) {
            int t = __shfl_up_sync(0xffffffffu, v, off);
            if (lane >= off) v += t;
        }
        if (idx < SCAN_NB) g_part[idx] = run + v - orig;  // exclusive
        run += __shfl_sync(0xffffffffu, v, 31);
    }
}

__global__ void scan3_kernel() {
    int i = blockIdx.x * blockDim.x + threadIdx.x;
    if (i >= N_NODES) return;
    int inc = g_incl[i] + g_part[i >> 10];
    int c = g_cnt[i];
    g_row_start[i] = inc - c;
    g_row_end[i] = inc;
    g_cursor[i] = inc - c;
}

__global__ void scatter_kernel(const void* __restrict__ ei) {
    int gid = blockIdx.x * blockDim.x + threadIdx.x;
    if (gid >= E_EDGES) return;
    int src, dst;
    load_edge(ei, gid, src, dst);
    int pos = atomicAdd(&g_cursor[dst], 1);
    g_csr_src[pos] = src;
}

// ---------------- GEMM1 (tf32 mma, cp.async double-buffered): h1 = x @ W1 ----------------
// CTA tile 128x64, BK=16, 8 warps (4x2), warp 32x32 via m16n8k8.
__global__ __launch_bounds__(256) void gemm1_kernel(const float* __restrict__ x,
                                                    const float* __restrict__ W1) {
    __shared__ float As[2][128][20];   // pitch 20 -> 16B-aligned rows, conflict-free
    __shared__ float Bs[2][16][68];    // pitch 68 -> 16B-aligned rows, conflict-free
    const int tid = threadIdx.x;
    const int warp = tid >> 5, lane = tid & 31;
    const int gid = lane >> 2, tig = lane & 3;
    const int mw = (warp >> 1) * 32;
    const int nw = (warp & 1) * 32;
    const int block_row = blockIdx.x * 128;

    // per-thread load coords
    const int ar = tid >> 2;          // A row (0..127 over idx<512, 2 chunks)
    const int ac4 = tid & 3;          // A col group
    const int bkk = tid >> 4, bn4 = tid & 15;

    float acc[2][4][4];
#pragma unroll
    for (int mt = 0; mt < 2; mt++)
#pragma unroll
        for (int nt = 0; nt < 4; nt++)
#pragma unroll
            for (int j = 0; j < 4; j++) acc[mt][nt][j] = 0.f;

    // stage loader
    auto load_stage = [&](int st, int k0) {
        // A: 128 x 16 = 512 float4 -> 2 per thread
#pragma unroll
        for (int p = 0; p < 2; p++) {
            int r = ar + p * 64;
            int gr = block_row + r;
            if (gr >= N_NODES) gr = N_NODES - 1;   // clamp (rows discarded later)
            cp16(&As[st][r][ac4 * 4], x + (size_t)gr * FIN + k0 + ac4 * 4);
        }
        // B: 16 x 64 = 256 float4 -> 1 per thread
        cp16(&Bs[st][bkk][bn4 * 4], W1 + (size_t)(k0 + bkk) * 64 + bn4 * 4);
    };

    load_stage(0, 0);
    cp_commit();

    int st = 0;
    for (int k0 = 0; k0 < FIN; k0 += 16, st ^= 1) {
        if (k0 + 16 < FIN) load_stage(st ^ 1, k0 + 16);
        cp_commit();
        cp_wait<1>();
        __syncthreads();
#pragma unroll
        for (int kk = 0; kk < 16; kk += 8) {
            float a[2][4];
#pragma unroll
            for (int mt = 0; mt < 2; mt++) {
                int r = mw + mt * 16;
                a[mt][0] = As[st][r + gid][kk + tig];
                a[mt][1] = As[st][r + gid + 8][kk + tig];
                a[mt][2] = As[st][r + gid][kk + tig + 4];
                a[mt][3] = As[st][r + gid + 8][kk + tig + 4];
            }
            float b[4][2];
#pragma unroll
            for (int nt = 0; nt < 4; nt++) {
                b[nt][0] = Bs[st][kk + tig][nw + nt * 8 + gid];
                b[nt][1] = Bs[st][kk + tig + 4][nw + nt * 8 + gid];
            }
#pragma unroll
            for (int mt = 0; mt < 2; mt++)
#pragma unroll
                for (int nt = 0; nt < 4; nt++)
                    mma_tf32(acc[mt][nt], a[mt], b[nt]);
        }
        __syncthreads();
    }

    // epilogue: fp16 only
#pragma unroll
    for (int mt = 0; mt < 2; mt++) {
#pragma unroll
        for (int nt = 0; nt < 4; nt++) {
            int r0 = block_row + mw + mt * 16 + gid;
            int c = nw + nt * 8 + 2 * tig;
            if (r0 < N_NODES)
                *(__half2*)(g_h1h + (size_t)r0 * 64 + c) =
                    __floats2half2_rn(acc[mt][nt][0], acc[mt][nt][1]);
            if (r0 + 8 < N_NODES)
                *(__half2*)(g_h1h + (size_t)(r0 + 8) * 64 + c) =
                    __floats2half2_rn(acc[mt][nt][2], acc[mt][nt][3]);
        }
    }
}

// ---------------- node1: attention logits (fp16 h source) ----------------
__global__ __launch_bounds__(256) void node1_kernel(const float* __restrict__ a1s,
                                                    const float* __restrict__ a1d) {
    int t = blockIdx.x * blockDim.x + threadIdx.x;
    int i = t >> 3, l = t & 7;
    if (i >= N_NODES) return;
    uint4 hv = *(const uint4*)(g_h1h + (size_t)i * 64 + l * 8);
    float2 f0 = __half22float2(*(__half2*)&hv.x);
    float2 f1 = __half22float2(*(__half2*)&hv.y);
    float2 f2 = __half22float2(*(__half2*)&hv.z);
    float2 f3 = __half22float2(*(__half2*)&hv.w);
    const float* as = a1s + l * 8;
    const float* ad = a1d + l * 8;
    float vs = f0.x * as[0] + f0.y * as[1] + f1.x * as[2] + f1.y * as[3] +
               f2.x * as[4] + f2.y * as[5] + f3.x * as[6] + f3.y * as[7];
    float vd = f0.x * ad[0] + f0.y * ad[1] + f1.x * ad[2] + f1.y * ad[3] +
               f2.x * ad[4] + f2.y * ad[5] + f3.x * ad[6] + f3.y * ad[7];
    g_al1s[i * 8 + l] = vs;
    g_al1d[i * 8 + l] = vd;
}

// ---------------- edge1 (CSR pull): one warp per dst node ----------------
__global__ __launch_bounds__(256) void edge1_csr_kernel() {
    int w = (blockIdx.x * blockDim.x + threadIdx.x) >> 5;
    if (w >= N_NODES) return;
    const int lane = threadIdx.x & 31;
    const int sub = lane >> 3, l = lane & 7;
    const int i = w;

    float ald = g_al1d[i * 8 + l];
    float acc[8];
#pragma unroll
    for (int j = 0; j < 8; j++) acc[j] = 0.f;
    float wsum = 0.f;

    if (sub == 0) {  // self-loop
        float e = g_al1s[i * 8 + l] + ald;
        float ws = expf(leaky(e));
        wsum = ws;
        uint4 hv = *(const uint4*)(g_h1h + (size_t)i * 64 + l * 8);
        float2 f0 = __half22float2(*(__half2*)&hv.x);
        float2 f1 = __half22float2(*(__half2*)&hv.y);
        float2 f2 = __half22float2(*(__half2*)&hv.z);
        float2 f3 = __half22float2(*(__half2*)&hv.w);
        acc[0] = ws * f0.x; acc[1] = ws * f0.y;
        acc[2] = ws * f1.x; acc[3] = ws * f1.y;
        acc[4] = ws * f2.x; acc[5] = ws * f2.y;
        acc[6] = ws * f3.x; acc[7] = ws * f3.y;
    }

    const int start = g_row_start[i], end = g_row_end[i];
    for (int p = start + sub; p < end; p += 4) {
        int src = g_csr_src[p];
        float e = g_al1s[src * 8 + l] + ald;
        float wv = expf(leaky(e));
        wsum += wv;
        uint4 hv = *(const uint4*)(g_h1h + (size_t)src * 64 + l * 8);
        float2 f0 = __half22float2(*(__half2*)&hv.x);
        float2 f1 = __half22float2(*(__half2*)&hv.y);
        float2 f2 = __half22float2(*(__half2*)&hv.z);
        float2 f3 = __half22float2(*(__half2*)&hv.w);
        acc[0] += wv * f0.x; acc[1] += wv * f0.y;
        acc[2] += wv * f1.x; acc[3] += wv * f1.y;
        acc[4] += wv * f2.x; acc[5] += wv * f2.y;
        acc[6] += wv * f3.x; acc[7] += wv * f3.y;
    }

#pragma unroll
    for (int off = 8; off <= 16; off <<= 1) {
        wsum += __shfl_xor_sync(0xffffffffu, wsum, off);
#pragma unroll
        for (int j = 0; j < 8; j++)
            acc[j] += __shfl_xor_sync(0xffffffffu, acc[j], off);
    }

    if (sub == 0) {
        float inv = 1.f / wsum;
        *(float4*)(g_acc1 + (size_t)i * 64 + l * 8) =
            make_float4(acc[0] * inv, acc[1] * inv, acc[2] * inv, acc[3] * inv);
        *(float4*)(g_acc1 + (size_t)i * 64 + l * 8 + 4) =
            make_float4(acc[4] * inv, acc[5] * inv, acc[6] * inv, acc[7] * inv);
    }
}

// ---------------- final1: bias + ELU + GEMM2 + layer-2 attn logits ----------------
__global__ __launch_bounds__(256) void final1_kernel(const float* __restrict__ W2,
                                                     const float* __restrict__ b1,
                                                     const float* __restrict__ a2s,
                                                     const float* __restrict__ a2d) {
    __shared__ float W2s[64 * 16];
    __shared__ float vbuf[16][64];
    const int tid = threadIdx.x;
    for (int j = tid; j < 64 * 16; j += 256) W2s[j] = W2[j];
    __syncthreads();

    int nl = tid >> 4, c = tid & 15;
    int i = blockIdx.x * 16 + nl;

    if (i < N_NODES) {
        float4 a = *(const float4*)(g_acc1 + (size_t)i * 64 + c * 4);
        float4 bb = *(const float4*)(b1 + c * 4);
        float v0 = a.x + bb.x;
        float v1 = a.y + bb.y;
        float v2 = a.z + bb.z;
        float v3 = a.w + bb.w;
        v0 = v0 > 0.f ? v0 : expf(v0) - 1.f;
        v1 = v1 > 0.f ? v1 : expf(v1) - 1.f;
        v2 = v2 > 0.f ? v2 : expf(v2) - 1.f;
        v3 = v3 > 0.f ? v3 : expf(v3) - 1.f;
        vbuf[nl][c * 4 + 0] = v0;
        vbuf[nl][c * 4 + 1] = v1;
        vbuf[nl][c * 4 + 2] = v2;
        vbuf[nl][c * 4 + 3] = v3;
    }
    __syncwarp();

    float h2c = 0.f;
    if (i < N_NODES) {
#pragma unroll
        for (int j = 0; j < 64; j++) h2c += vbuf[nl][j] * W2s[j * 16 + c];
    }
    float als = h2c * a2s[c];
    float ald = h2c * a2d[c];
#pragma unroll
    for (int off = 8; off > 0; off >>= 1) {
        als += __shfl_down_sync(0xffffffffu, als, off, 16);
        ald += __shfl_down_sync(0xffffffffu, ald, off, 16);
    }
    als = __shfl_sync(0xffffffffu, als, 0, 16);
    ald = __shfl_sync(0xffffffffu, ald, 0, 16);

    if (i < N_NODES) {
        g_h2h[i * 16 + c] = __float2half_rn(h2c);
        if (c == 0) {
            g_al2s[i] = als;
            g_al2d[i] = ald;
        }
    }
}

// ---------------- edge2 (CSR pull): one warp per dst node ----------------
__global__ __launch_bounds__(256) void edge2_csr_kernel() {
    int w = (blockIdx.x * blockDim.x + threadIdx.x) >> 5;
    if (w >= N_NODES) return;
    const int lane = threadIdx.x & 31;
    const int sub = lane >> 2, l = lane & 3;
    const int i = w;

    float ald = g_al2d[i];
    float acc[4];
#pragma unroll
    for (int j = 0; j < 4; j++) acc[j] = 0.f;
    float wsum = 0.f;

    if (sub == 0) {  // self-loop
        float ws = expf(leaky(g_al2s[i] + ald));
        wsum = ws;
        uint2 hv = *(const uint2*)(g_h2h + (size_t)i * 16 + l * 4);
        float2 f0 = __half22float2(*(__half2*)&hv.x);
        float2 f1 = __half22float2(*(__half2*)&hv.y);
        acc[0] = ws * f0.x; acc[1] = ws * f0.y;
        acc[2] = ws * f1.x; acc[3] = ws * f1.y;
    }

    const int start = g_row_start[i], end = g_row_end[i];
    for (int p = start + sub; p < end; p += 8) {
        int src = g_csr_src[p];
        float wv = expf(leaky(g_al2s[src] + ald));
        wsum += wv;
        uint2 hv = *(const uint2*)(g_h2h + (size_t)src * 16 + l * 4);
        float2 f0 = __half22float2(*(__half2*)&hv.x);
        float2 f1 = __half22float2(*(__half2*)&hv.y);
        acc[0] += wv * f0.x; acc[1] += wv * f0.y;
        acc[2] += wv * f1.x; acc[3] += wv * f1.y;
    }

#pragma unroll
    for (int off = 4; off <= 16; off <<= 1) {
        wsum += __shfl_xor_sync(0xffffffffu, wsum, off);
#pragma unroll
        for (int j = 0; j < 4; j++)
            acc[j] += __shfl_xor_sync(0xffffffffu, acc[j], off);
    }

    if (sub == 0) {
        float inv = 1.f / wsum;
        *(float4*)(g_acc2 + (size_t)i * 16 + l * 4) =
            make_float4(acc[0] * inv, acc[1] * inv, acc[2] * inv, acc[3] * inv);
    }
}

// ---------------- final2: bias + log_softmax ----------------
__global__ __launch_bounds__(256) void final2_kernel(const float* __restrict__ b2,
                                                     float* __restrict__ out) {
    int tid = threadIdx.x;
    int nl = tid >> 4, c = tid & 15;
    int i = blockIdx.x * 16 + nl;
    float o = -1e30f;
    if (i < N_NODES) o = g_acc2[i * 16 + c] + b2[c];
    float m = o;
#pragma unroll
    for (int off = 8; off > 0; off >>= 1)
        m = fmaxf(m, __shfl_xor_sync(0xffffffffu, m, off, 16));
    float ex = expf(o - m);
    float sum = ex;
#pragma unroll
    for (int off = 8; off > 0; off >>= 1)
        sum += __shfl_xor_sync(0xffffffffu, sum, off, 16);
    if (i < N_NODES) out[i * 16 + c] = o - m - logf(sum);
}

// ---------------- launch ----------------
extern "C" void kernel_launch(void* const* d_in, const int* in_sizes, int n_in,
                              void* d_out, int out_size) {
    const float* x   = (const float*)d_in[0];
    const void*  ei  = d_in[1];
    const float* W1  = (const float*)d_in[2];
    const float* a1s = (const float*)d_in[3];
    const float* a1d = (const float*)d_in[4];
    const float* b1  = (const float*)d_in[5];
    const float* W2  = (const float*)d_in[6];
    const float* a2s = (const float*)d_in[7];
    const float* a2d = (const float*)d_in[8];
    const float* b2  = (const float*)d_in[9];
    float* out = (float*)d_out;

    detect_kernel<<<1, 256>>>((const int*)ei);
    // CSR build (reused by both layers)
    zero_kernel<<<(N_NODES + 255) / 256, 256>>>();
    hist_kernel<<<(E_EDGES + 255) / 256, 256>>>(ei);
    scan1_kernel<<<SCAN_NB, 1024>>>();
    scan2_kernel<<<1, 32>>>();
    scan3_kernel<<<(N_NODES + 255) / 256, 256>>>();
    scatter_kernel<<<(E_EDGES + 255) / 256, 256>>>(ei);
    // layer 1
    gemm1_kernel<<<(N_NODES + 127) / 128, 256>>>(x, W1);
    node1_kernel<<<(N_NODES * 8 + 255) / 256, 256>>>(a1s, a1d);
    edge1_csr_kernel<<<(N_NODES * 32 + 255) / 256, 256>>>();
    final1_kernel<<<(N_NODES + 15) / 16, 256>>>(W2, b1, a2s, a2d);
    // layer 2
    edge2_csr_kernel<<<(N_NODES * 32 + 255) / 256, 256>>>();
    final2_kernel<<<(N_NODES + 15) / 16, 256>>>(b2, out);
}

// round 9
// speedup vs baseline: 1.3984x; 1.3984x over previous
#include <cuda_runtime.h>
#include <cuda_fp16.h>

#define N_NODES 100000
#define E_EDGES 1600000
#define FIN 512
#define HC1 64
#define H1 8
#define C2 16
#define NEG_SLOPE 0.2f
#define SCAN_NB ((N_NODES + 1023) / 1024)

// ---------------- scratch (static __device__, allocation-free) ----------------
__device__ __half g_h1h [(size_t)N_NODES * HC1];   // fp16 h1 (only copy)
__device__ float  g_al1s[(size_t)N_NODES * H1];
__device__ float  g_al1d[(size_t)N_NODES * H1];
__device__ float  g_acc1[(size_t)N_NODES * HC1];   // NORMALIZED layer-1 aggregate
__device__ __half g_h2h [(size_t)N_NODES * C2];    // fp16 h2 for edge2 gather
__device__ float  g_al2s[(size_t)N_NODES];
__device__ float  g_al2d[(size_t)N_NODES];
__device__ float  g_acc2[(size_t)N_NODES * C2];    // NORMALIZED layer-2 aggregate
__device__ int    g_is64;

// CSR build scratch
__device__ int g_cnt      [N_NODES];
__device__ int g_incl     [N_NODES];
__device__ int g_part     [SCAN_NB + 1];
__device__ int g_row_start[N_NODES];
__device__ int g_row_end  [N_NODES];
__device__ int g_cursor   [N_NODES];
__device__ int g_csr_src  [E_EDGES];

__device__ __forceinline__ float leaky(float e) { return e > 0.f ? e : NEG_SLOPE * e; }

__device__ __forceinline__ float to_tf32(float f) {
    unsigned u;
    asm("cvt.rna.tf32.f32 %0, %1;" : "=r"(u) : "f"(f));
    return __uint_as_float(u);
}

// m16n8k8 tf32 mma, row.col, f32 accumulate
__device__ __forceinline__ void mma_tf32(float* d, const float* a, const float* b) {
    asm volatile(
        "mma.sync.aligned.m16n8k8.row.col.f32.tf32.tf32.f32 "
        "{%0,%1,%2,%3}, {%4,%5,%6,%7}, {%8,%9}, {%0,%1,%2,%3};\n"
        : "+f"(d[0]), "+f"(d[1]), "+f"(d[2]), "+f"(d[3])
        : "r"(__float_as_uint(a[0])), "r"(__float_as_uint(a[1])),
          "r"(__float_as_uint(a[2])), "r"(__float_as_uint(a[3])),
          "r"(__float_as_uint(b[0])), "r"(__float_as_uint(b[1])));
}

// ---------------- edge dtype detection (int64 vs int32) ----------------
__global__ void detect_kernel(const int* __restrict__ ei_words) {
    __shared__ int nz;
    if (threadIdx.x == 0) nz = 0;
    __syncthreads();
    for (int i = threadIdx.x; i < 4096; i += blockDim.x)
        if (ei_words[2 * i + 1] != 0) nz = 1;
    __syncthreads();
    if (threadIdx.x == 0) g_is64 = (nz == 0);
}

__device__ __forceinline__ void load_edge(const void* ei, int gid, int& src, int& dst) {
    if (g_is64) {
        const long long* p = (const long long*)ei;
        src = (int)p[gid];
        dst = (int)p[E_EDGES + gid];
    } else {
        const int* p = (const int*)ei;
        src = p[gid];
        dst = p[E_EDGES + gid];
    }
}

__device__ __forceinline__ int load_dst(const void* ei, int gid) {
    if (g_is64) return (int)((const long long*)ei)[E_EDGES + gid];
    return ((const int*)ei)[E_EDGES + gid];
}

// ---------------- CSR build ----------------
__global__ void zero_kernel() {
    int i = blockIdx.x * blockDim.x + threadIdx.x;
    if (i < N_NODES) g_cnt[i] = 0;
}

__global__ void hist_kernel(const void* __restrict__ ei) {
    int gid = blockIdx.x * blockDim.x + threadIdx.x;
    if (gid >= E_EDGES) return;
    atomicAdd(&g_cnt[load_dst(ei, gid)], 1);
}

__global__ __launch_bounds__(1024) void scan1_kernel() {
    __shared__ int sm[1024];
    int i = blockIdx.x * 1024 + threadIdx.x;
    sm[threadIdx.x] = (i < N_NODES) ? g_cnt[i] : 0;
    __syncthreads();
#pragma unroll
    for (int off = 1; off < 1024; off <<= 1) {
        int t = (threadIdx.x >= off) ? sm[threadIdx.x - off] : 0;
        __syncthreads();
        sm[threadIdx.x] += t;
        __syncthreads();
    }
    if (i < N_NODES) g_incl[i] = sm[threadIdx.x];
    if (threadIdx.x == 1023) g_part[blockIdx.x] = sm[1023];
}

// warp-parallel exclusive scan of g_part (SCAN_NB entries), one warp
__global__ void scan2_kernel() {
    int lane = threadIdx.x;
    int run = 0;
    for (int b0 = 0; b0 < SCAN_NB; b0 += 32) {
        int idx = b0 + lane;
        int orig = (idx < SCAN_NB) ? g_part[idx] : 0;
        int v = orig;
#pragma unroll
        for (int off = 1; off < 32; off <<= 1) {
            int t = __shfl_up_sync(0xffffffffu, v, off);
            if (lane >= off) v += t;
        }
        if (idx < SCAN_NB) g_part[idx] = run + v - orig;  // exclusive
        run += __shfl_sync(0xffffffffu, v, 31);
    }
}

__global__ void scan3_kernel() {
    int i = blockIdx.x * blockDim.x + threadIdx.x;
    if (i >= N_NODES) return;
    int inc = g_incl[i] + g_part[i >> 10];
    int c = g_cnt[i];
    g_row_start[i] = inc - c;
    g_row_end[i] = inc;
    g_cursor[i] = inc - c;
}

__global__ void scatter_kernel(const void* __restrict__ ei) {
    int gid = blockIdx.x * blockDim.x + threadIdx.x;
    if (gid >= E_EDGES) return;
    int src, dst;
    load_edge(ei, gid, src, dst);
    int pos = atomicAdd(&g_cursor[dst], 1);
    g_csr_src[pos] = src;
}

// ---------------- GEMM1 (tensor cores, tf32): h1 = x @ W1, fused attn logits ----------------
// CTA tile 128x64, BK=32, 8 warps (4x2), each warp 32x32 via m16n8k8 mma.
// Epilogue: fp16 h1 + per-head logits al1s/al1d from fp32 accumulators (node1 fused away).
__global__ __launch_bounds__(256) void gemm1_kernel(const float* __restrict__ x,
                                                    const float* __restrict__ W1,
                                                    const float* __restrict__ a1s,
                                                    const float* __restrict__ a1d) {
    __shared__ float As[128][36];
    __shared__ float Bs[32][72];
    const int tid = threadIdx.x;
    const int warp = tid >> 5, lane = tid & 31;
    const int gid = lane >> 2, tig = lane & 3;
    const int mw = (warp >> 1) * 32;
    const int nw = (warp & 1) * 32;
    const int block_row = blockIdx.x * 128;

    float acc[2][4][4];
#pragma unroll
    for (int mt = 0; mt < 2; mt++)
#pragma unroll
        for (int nt = 0; nt < 4; nt++)
#pragma unroll
            for (int j = 0; j < 4; j++) acc[mt][nt][j] = 0.f;

    for (int k0 = 0; k0 < FIN; k0 += 32) {
#pragma unroll
        for (int p = 0; p < 4; p++) {
            int idx = tid + p * 256;
            int r = idx >> 3, c4 = idx & 7;
            int gr = block_row + r;
            float4 v = make_float4(0.f, 0.f, 0.f, 0.f);
            if (gr < N_NODES)
                v = *(const float4*)(x + (size_t)gr * FIN + k0 + c4 * 4);
            v.x = to_tf32(v.x); v.y = to_tf32(v.y);
            v.z = to_tf32(v.z); v.w = to_tf32(v.w);
            *(float4*)&As[r][c4 * 4] = v;
        }
#pragma unroll
        for (int p = 0; p < 2; p++) {
            int idx = tid + p * 256;
            int kk = idx >> 4, n4 = idx & 15;
            float4 v = *(const float4*)(W1 + (size_t)(k0 + kk) * 64 + n4 * 4);
            v.x = to_tf32(v.x); v.y = to_tf32(v.y);
            v.z = to_tf32(v.z); v.w = to_tf32(v.w);
            *(float4*)&Bs[kk][n4 * 4] = v;
        }
        __syncthreads();
#pragma unroll
        for (int kk = 0; kk < 32; kk += 8) {
            float a[2][4];
#pragma unroll
            for (int mt = 0; mt < 2; mt++) {
                int r = mw + mt * 16;
                a[mt][0] = As[r + gid][kk + tig];
                a[mt][1] = As[r + gid + 8][kk + tig];
                a[mt][2] = As[r + gid][kk + tig + 4];
                a[mt][3] = As[r + gid + 8][kk + tig + 4];
            }
            float b[4][2];
#pragma unroll
            for (int nt = 0; nt < 4; nt++) {
                b[nt][0] = Bs[kk + tig][nw + nt * 8 + gid];
                b[nt][1] = Bs[kk + tig + 4][nw + nt * 8 + gid];
            }
#pragma unroll
            for (int mt = 0; mt < 2; mt++)
#pragma unroll
                for (int nt = 0; nt < 4; nt++)
                    mma_tf32(acc[mt][nt], a[mt], b[nt]);
        }
        __syncthreads();
    }

    // ---- epilogue: fp16 h1 + fused per-head attention logits ----
#pragma unroll
    for (int mt = 0; mt < 2; mt++) {
#pragma unroll
        for (int nt = 0; nt < 4; nt++) {
            int r0 = block_row + mw + mt * 16 + gid;
            int c = nw + nt * 8 + 2 * tig;
            int l = (nw + nt * 8) >> 3;          // head for this nt tile
            float as0 = __ldg(a1s + l * 8 + 2 * tig);
            float as1 = __ldg(a1s + l * 8 + 2 * tig + 1);
            float ad0 = __ldg(a1d + l * 8 + 2 * tig);
            float ad1 = __ldg(a1d + l * 8 + 2 * tig + 1);

            float vs  = acc[mt][nt][0] * as0 + acc[mt][nt][1] * as1;   // row r0
            float vd  = acc[mt][nt][0] * ad0 + acc[mt][nt][1] * ad1;
            float vs2 = acc[mt][nt][2] * as0 + acc[mt][nt][3] * as1;   // row r0+8
            float vd2 = acc[mt][nt][2] * ad0 + acc[mt][nt][3] * ad1;
#pragma unroll
            for (int off = 1; off <= 2; off <<= 1) {
                vs  += __shfl_xor_sync(0xffffffffu, vs,  off);
                vd  += __shfl_xor_sync(0xffffffffu, vd,  off);
                vs2 += __shfl_xor_sync(0xffffffffu, vs2, off);
                vd2 += __shfl_xor_sync(0xffffffffu, vd2, off);
            }

            if (r0 < N_NODES) {
                *(__half2*)(g_h1h + (size_t)r0 * 64 + c) =
                    __floats2half2_rn(acc[mt][nt][0], acc[mt][nt][1]);
                if (tig == 0) {
                    g_al1s[r0 * 8 + l] = vs;
                    g_al1d[r0 * 8 + l] = vd;
                }
            }
            if (r0 + 8 < N_NODES) {
                *(__half2*)(g_h1h + (size_t)(r0 + 8) * 64 + c) =
                    __floats2half2_rn(acc[mt][nt][2], acc[mt][nt][3]);
                if (tig == 0) {
                    g_al1s[(r0 + 8) * 8 + l] = vs2;
                    g_al1d[(r0 + 8) * 8 + l] = vd2;
                }
            }
        }
    }
}

// ---------------- edge1 (CSR pull): one warp per dst node ----------------
__global__ __launch_bounds__(256) void edge1_csr_kernel() {
    int w = (blockIdx.x * blockDim.x + threadIdx.x) >> 5;
    if (w >= N_NODES) return;
    const int lane = threadIdx.x & 31;
    const int sub = lane >> 3, l = lane & 7;
    const int i = w;

    float ald = g_al1d[i * 8 + l];
    float acc[8];
#pragma unroll
    for (int j = 0; j < 8; j++) acc[j] = 0.f;
    float wsum = 0.f;

    if (sub == 0) {  // self-loop
        float e = g_al1s[i * 8 + l] + ald;
        float ws = expf(leaky(e));
        wsum = ws;
        uint4 hv = *(const uint4*)(g_h1h + (size_t)i * 64 + l * 8);
        float2 f0 = __half22float2(*(__half2*)&hv.x);
        float2 f1 = __half22float2(*(__half2*)&hv.y);
        float2 f2 = __half22float2(*(__half2*)&hv.z);
        float2 f3 = __half22float2(*(__half2*)&hv.w);
        acc[0] = ws * f0.x; acc[1] = ws * f0.y;
        acc[2] = ws * f1.x; acc[3] = ws * f1.y;
        acc[4] = ws * f2.x; acc[5] = ws * f2.y;
        acc[6] = ws * f3.x; acc[7] = ws * f3.y;
    }

    const int start = g_row_start[i], end = g_row_end[i];
    for (int p = start + sub; p < end; p += 4) {
        int src = g_csr_src[p];
        float e = g_al1s[src * 8 + l] + ald;
        float wv = expf(leaky(e));
        wsum += wv;
        uint4 hv = *(const uint4*)(g_h1h + (size_t)src * 64 + l * 8);
        float2 f0 = __half22float2(*(__half2*)&hv.x);
        float2 f1 = __half22float2(*(__half2*)&hv.y);
        float2 f2 = __half22float2(*(__half2*)&hv.z);
        float2 f3 = __half22float2(*(__half2*)&hv.w);
        acc[0] += wv * f0.x; acc[1] += wv * f0.y;
        acc[2] += wv * f1.x; acc[3] += wv * f1.y;
        acc[4] += wv * f2.x; acc[5] += wv * f2.y;
        acc[6] += wv * f3.x; acc[7] += wv * f3.y;
    }

#pragma unroll
    for (int off = 8; off <= 16; off <<= 1) {
        wsum += __shfl_xor_sync(0xffffffffu, wsum, off);
#pragma unroll
        for (int j = 0; j < 8; j++)
            acc[j] += __shfl_xor_sync(0xffffffffu, acc[j], off);
    }

    if (sub == 0) {
        float inv = 1.f / wsum;
        *(float4*)(g_acc1 + (size_t)i * 64 + l * 8) =
            make_float4(acc[0] * inv, acc[1] * inv, acc[2] * inv, acc[3] * inv);
        *(float4*)(g_acc1 + (size_t)i * 64 + l * 8 + 4) =
            make_float4(acc[4] * inv, acc[5] * inv, acc[6] * inv, acc[7] * inv);
    }
}

// ---------------- final1: bias + ELU + GEMM2 + layer-2 attn logits ----------------
__global__ __launch_bounds__(256) void final1_kernel(const float* __restrict__ W2,
                                                     const float* __restrict__ b1,
                                                     const float* __restrict__ a2s,
                                                     const float* __restrict__ a2d) {
    __shared__ float W2s[64 * 16];
    __shared__ float vbuf[16][64];
    const int tid = threadIdx.x;
    for (int j = tid; j < 64 * 16; j += 256) W2s[j] = W2[j];
    __syncthreads();

    int nl = tid >> 4, c = tid & 15;
    int i = blockIdx.x * 16 + nl;

    if (i < N_NODES) {
        float4 a = *(const float4*)(g_acc1 + (size_t)i * 64 + c * 4);
        float4 bb = *(const float4*)(b1 + c * 4);
        float v0 = a.x + bb.x;
        float v1 = a.y + bb.y;
        float v2 = a.z + bb.z;
        float v3 = a.w + bb.w;
        v0 = v0 > 0.f ? v0 : expf(v0) - 1.f;
        v1 = v1 > 0.f ? v1 : expf(v1) - 1.f;
        v2 = v2 > 0.f ? v2 : expf(v2) - 1.f;
        v3 = v3 > 0.f ? v3 : expf(v3) - 1.f;
        vbuf[nl][c * 4 + 0] = v0;
        vbuf[nl][c * 4 + 1] = v1;
        vbuf[nl][c * 4 + 2] = v2;
        vbuf[nl][c * 4 + 3] = v3;
    }
    __syncwarp();

    float h2c = 0.f;
    if (i < N_NODES) {
#pragma unroll
        for (int j = 0; j < 64; j++) h2c += vbuf[nl][j] * W2s[j * 16 + c];
    }
    float als = h2c * a2s[c];
    float ald = h2c * a2d[c];
#pragma unroll
    for (int off = 8; off > 0; off >>= 1) {
        als += __shfl_down_sync(0xffffffffu, als, off, 16);
        ald += __shfl_down_sync(0xffffffffu, ald, off, 16);
    }
    als = __shfl_sync(0xffffffffu, als, 0, 16);
    ald = __shfl_sync(0xffffffffu, ald, 0, 16);

    if (i < N_NODES) {
        g_h2h[i * 16 + c] = __float2half_rn(h2c);
        if (c == 0) {
            g_al2s[i] = als;
            g_al2d[i] = ald;
        }
    }
}

// ---------------- edge2 (CSR pull): one warp per dst node ----------------
__global__ __launch_bounds__(256) void edge2_csr_kernel() {
    int w = (blockIdx.x * blockDim.x + threadIdx.x) >> 5;
    if (w >= N_NODES) return;
    const int lane = threadIdx.x & 31;
    const int sub = lane >> 2, l = lane & 3;
    const int i = w;

    float ald = g_al2d[i];
    float acc[4];
#pragma unroll
    for (int j = 0; j < 4; j++) acc[j] = 0.f;
    float wsum = 0.f;

    if (sub == 0) {  // self-loop
        float ws = expf(leaky(g_al2s[i] + ald));
        wsum = ws;
        uint2 hv = *(const uint2*)(g_h2h + (size_t)i * 16 + l * 4);
        float2 f0 = __half22float2(*(__half2*)&hv.x);
        float2 f1 = __half22float2(*(__half2*)&hv.y);
        acc[0] = ws * f0.x; acc[1] = ws * f0.y;
        acc[2] = ws * f1.x; acc[3] = ws * f1.y;
    }

    const int start = g_row_start[i], end = g_row_end[i];
    for (int p = start + sub; p < end; p += 8) {
        int src = g_csr_src[p];
        float wv = expf(leaky(g_al2s[src] + ald));
        wsum += wv;
        uint2 hv = *(const uint2*)(g_h2h + (size_t)src * 16 + l * 4);
        float2 f0 = __half22float2(*(__half2*)&hv.x);
        float2 f1 = __half22float2(*(__half2*)&hv.y);
        acc[0] += wv * f0.x; acc[1] += wv * f0.y;
        acc[2] += wv * f1.x; acc[3] += wv * f1.y;
    }

#pragma unroll
    for (int off = 4; off <= 16; off <<= 1) {
        wsum += __shfl_xor_sync(0xffffffffu, wsum, off);
#pragma unroll
        for (int j = 0; j < 4; j++)
            acc[j] += __shfl_xor_sync(0xffffffffu, acc[j], off);
    }

    if (sub == 0) {
        float inv = 1.f / wsum;
        *(float4*)(g_acc2 + (size_t)i * 16 + l * 4) =
            make_float4(acc[0] * inv, acc[1] * inv, acc[2] * inv, acc[3] * inv);
    }
}

// ---------------- final2: bias + log_softmax ----------------
__global__ __launch_bounds__(256) void final2_kernel(const float* __restrict__ b2,
                                                     float* __restrict__ out) {
    int tid = threadIdx.x;
    int nl = tid >> 4, c = tid & 15;
    int i = blockIdx.x * 16 + nl;
    float o = -1e30f;
    if (i < N_NODES) o = g_acc2[i * 16 + c] + b2[c];
    float m = o;
#pragma unroll
    for (int off = 8; off > 0; off >>= 1)
        m = fmaxf(m, __shfl_xor_sync(0xffffffffu, m, off, 16));
    float ex = expf(o - m);
    float sum = ex;
#pragma unroll
    for (int off = 8; off > 0; off >>= 1)
        sum += __shfl_xor_sync(0xffffffffu, sum, off, 16);
    if (i < N_NODES) out[i * 16 + c] = o - m - logf(sum);
}

// ---------------- launch ----------------
extern "C" void kernel_launch(void* const* d_in, const int* in_sizes, int n_in,
                              void* d_out, int out_size) {
    const float* x   = (const float*)d_in[0];
    const void*  ei  = d_in[1];
    const float* W1  = (const float*)d_in[2];
    const float* a1s = (const float*)d_in[3];
    const float* a1d = (const float*)d_in[4];
    const float* b1  = (const float*)d_in[5];
    const float* W2  = (const float*)d_in[6];
    const float* a2s = (const float*)d_in[7];
    const float* a2d = (const float*)d_in[8];
    const float* b2  = (const float*)d_in[9];
    float* out = (float*)d_out;

    detect_kernel<<<1, 256>>>((const int*)ei);
    // CSR build (reused by both layers)
    zero_kernel<<<(N_NODES + 255) / 256, 256>>>();
    hist_kernel<<<(E_EDGES + 255) / 256, 256>>>(ei);
    scan1_kernel<<<SCAN_NB, 1024>>>();
    scan2_kernel<<<1, 32>>>();
    scan3_kernel<<<(N_NODES + 255) / 256, 256>>>();
    scatter_kernel<<<(E_EDGES + 255) / 256, 256>>>(ei);
    // layer 1
    gemm1_kernel<<<(N_NODES + 127) / 128, 256>>>(x, W1, a1s, a1d);
    edge1_csr_kernel<<<(N_NODES * 32 + 255) / 256, 256>>>();
    final1_kernel<<<(N_NODES + 15) / 16, 256>>>(W2, b1, a2s, a2d);
    // layer 2
    edge2_csr_kernel<<<(N_NODES * 32 + 255) / 256, 256>>>();
    final2_kernel<<<(N_NODES + 15) / 16, 256>>>(b2, out);
}

// round 10
// speedup vs baseline: 1.4713x; 1.0521x over previous
#include <cuda_runtime.h>
#include <cuda_fp16.h>

#define N_NODES 100000
#define E_EDGES 1600000
#define FIN 512
#define HC1 64
#define H1 8
#define C2 16
#define NEG_SLOPE 0.2f
#define SCAN_NB ((N_NODES + 1023) / 1024)

// ---------------- scratch (static __device__, allocation-free) ----------------
__device__ __half g_h1h [(size_t)N_NODES * HC1];   // fp16 h1
__device__ float  g_al1s[(size_t)N_NODES * H1];
__device__ float  g_al1d[(size_t)N_NODES * H1];
__device__ float  g_acc1[(size_t)N_NODES * HC1];   // NORMALIZED layer-1 aggregate
__device__ __half g_h2h [(size_t)N_NODES * C2];    // fp16 h2 for edge2 gather
__device__ float  g_al2s[(size_t)N_NODES];
__device__ float  g_al2d[(size_t)N_NODES];
__device__ int    g_is64;
__device__ int    g_scan_ctr;

// CSR build scratch
__device__ int g_cnt      [N_NODES];
__device__ int g_incl     [N_NODES];
__device__ int g_part     [SCAN_NB + 1];
__device__ int g_row_start[N_NODES];
__device__ int g_row_end  [N_NODES];
__device__ int g_cursor   [N_NODES];
__device__ int g_csr_src  [E_EDGES];

__device__ __forceinline__ float leaky(float e) { return e > 0.f ? e : NEG_SLOPE * e; }

__device__ __forceinline__ float to_tf32(float f) {
    unsigned u;
    asm("cvt.rna.tf32.f32 %0, %1;" : "=r"(u) : "f"(f));
    return __uint_as_float(u);
}

// m16n8k8 tf32 mma, row.col, f32 accumulate
__device__ __forceinline__ void mma_tf32(float* d, const float* a, const float* b) {
    asm volatile(
        "mma.sync.aligned.m16n8k8.row.col.f32.tf32.tf32.f32 "
        "{%0,%1,%2,%3}, {%4,%5,%6,%7}, {%8,%9}, {%0,%1,%2,%3};\n"
        : "+f"(d[0]), "+f"(d[1]), "+f"(d[2]), "+f"(d[3])
        : "r"(__float_as_uint(a[0])), "r"(__float_as_uint(a[1])),
          "r"(__float_as_uint(a[2])), "r"(__float_as_uint(a[3])),
          "r"(__float_as_uint(b[0])), "r"(__float_as_uint(b[1])));
}

// ---------------- detect (int64 vs int32) + zero counters + reset scan ctr ----------------
__global__ void detect_zero_kernel(const int* __restrict__ ei_words) {
    int i = blockIdx.x * blockDim.x + threadIdx.x;
    if (i < N_NODES) g_cnt[i] = 0;
    if (blockIdx.x == 0) {
        __shared__ int nz;
        if (threadIdx.x == 0) nz = 0;
        __syncthreads();
        for (int j = threadIdx.x; j < 4096; j += blockDim.x)
            if (ei_words[2 * j + 1] != 0) nz = 1;
        __syncthreads();
        if (threadIdx.x == 0) {
            g_is64 = (nz == 0);
            g_scan_ctr = 0;
        }
    }
}

__device__ __forceinline__ void load_edge(const void* ei, int gid, int& src, int& dst) {
    if (g_is64) {
        const long long* p = (const long long*)ei;
        src = (int)p[gid];
        dst = (int)p[E_EDGES + gid];
    } else {
        const int* p = (const int*)ei;
        src = p[gid];
        dst = p[E_EDGES + gid];
    }
}

__device__ __forceinline__ int load_dst(const void* ei, int gid) {
    if (g_is64) return (int)((const long long*)ei)[E_EDGES + gid];
    return ((const int*)ei)[E_EDGES + gid];
}

// ---------------- CSR build ----------------
__global__ void hist_kernel(const void* __restrict__ ei) {
    int gid = blockIdx.x * blockDim.x + threadIdx.x;
    if (gid >= E_EDGES) return;
    atomicAdd(&g_cnt[load_dst(ei, gid)], 1);
}

// block-level inclusive scan + fused cross-block scan in the last-finishing block
__global__ __launch_bounds__(1024) void scan1_kernel() {
    __shared__ int sm[1024];
    __shared__ int is_last;
    int i = blockIdx.x * 1024 + threadIdx.x;
    sm[threadIdx.x] = (i < N_NODES) ? g_cnt[i] : 0;
    __syncthreads();
#pragma unroll
    for (int off = 1; off < 1024; off <<= 1) {
        int t = (threadIdx.x >= off) ? sm[threadIdx.x - off] : 0;
        __syncthreads();
        sm[threadIdx.x] += t;
        __syncthreads();
    }
    if (i < N_NODES) g_incl[i] = sm[threadIdx.x];
    if (threadIdx.x == 1023) g_part[blockIdx.x] = sm[1023];
    __threadfence();
    if (threadIdx.x == 0)
        is_last = (atomicAdd(&g_scan_ctr, 1) == (int)gridDim.x - 1);
    __syncthreads();
    if (is_last && threadIdx.x < 32) {
        int lane = threadIdx.x;
        int run = 0;
        for (int b0 = 0; b0 < SCAN_NB; b0 += 32) {
            int idx = b0 + lane;
            int orig = (idx < SCAN_NB) ? g_part[idx] : 0;
            int v = orig;
#pragma unroll
            for (int off = 1; off < 32; off <<= 1) {
                int t = __shfl_up_sync(0xffffffffu, v, off);
                if (lane >= off) v += t;
            }
            if (idx < SCAN_NB) g_part[idx] = run + v - orig;  // exclusive
            run += __shfl_sync(0xffffffffu, v, 31);
        }
    }
}

__global__ void scan3_kernel() {
    int i = blockIdx.x * blockDim.x + threadIdx.x;
    if (i >= N_NODES) return;
    int inc = g_incl[i] + g_part[i >> 10];
    int c = g_cnt[i];
    g_row_start[i] = inc - c;
    g_row_end[i] = inc;
    g_cursor[i] = inc - c;
}

__global__ void scatter_kernel(const void* __restrict__ ei) {
    int gid = blockIdx.x * blockDim.x + threadIdx.x;
    if (gid >= E_EDGES) return;
    int src, dst;
    load_edge(ei, gid, src, dst);
    int pos = atomicAdd(&g_cursor[dst], 1);
    g_csr_src[pos] = src;
}

// ---------------- GEMM1 (tf32 mma, register double-buffered): h1 = x @ W1 ----------------
// CTA tile 128x64, BK=32, 8 warps (4x2), warp 32x32 via m16n8k8; fused attn logits.
__global__ __launch_bounds__(256) void gemm1_kernel(const float* __restrict__ x,
                                                    const float* __restrict__ W1,
                                                    const float* __restrict__ a1s,
                                                    const float* __restrict__ a1d) {
    __shared__ float As[128][36];
    __shared__ float Bs[32][72];
    const int tid = threadIdx.x;
    const int warp = tid >> 5, lane = tid & 31;
    const int gid = lane >> 2, tig = lane & 3;
    const int mw = (warp >> 1) * 32;
    const int nw = (warp & 1) * 32;
    const int block_row = blockIdx.x * 128;

    float acc[2][4][4];
#pragma unroll
    for (int mt = 0; mt < 2; mt++)
#pragma unroll
        for (int nt = 0; nt < 4; nt++)
#pragma unroll
            for (int j = 0; j < 4; j++) acc[mt][nt][j] = 0.f;

    float4 aR[4], bR[2];
    const int ar_r[4]  = { (tid) >> 3, (tid + 256) >> 3, (tid + 512) >> 3, (tid + 768) >> 3 };
    const int ar_c4 = tid & 7;
    const int b_kk[2]  = { tid >> 4, (tid + 256) >> 4 };
    const int b_n4 = tid & 15;

    auto gload = [&](int k0) {
#pragma unroll
        for (int p = 0; p < 4; p++) {
            int gr = block_row + ar_r[p];
            if (gr >= N_NODES) gr = N_NODES - 1;   // clamp; rows discarded in epilogue
            aR[p] = *(const float4*)(x + (size_t)gr * FIN + k0 + ar_c4 * 4);
        }
#pragma unroll
        for (int p = 0; p < 2; p++)
            bR[p] = *(const float4*)(W1 + (size_t)(k0 + b_kk[p]) * 64 + b_n4 * 4);
    };
    auto sstore = [&]() {
#pragma unroll
        for (int p = 0; p < 4; p++) {
            float4 v = aR[p];
            v.x = to_tf32(v.x); v.y = to_tf32(v.y);
            v.z = to_tf32(v.z); v.w = to_tf32(v.w);
            *(float4*)&As[ar_r[p]][ar_c4 * 4] = v;
        }
#pragma unroll
        for (int p = 0; p < 2; p++) {
            float4 v = bR[p];
            v.x = to_tf32(v.x); v.y = to_tf32(v.y);
            v.z = to_tf32(v.z); v.w = to_tf32(v.w);
            *(float4*)&Bs[b_kk[p]][b_n4 * 4] = v;
        }
    };

    gload(0);
    sstore();
    __syncthreads();

    for (int k0 = 0; k0 < FIN; k0 += 32) {
        bool more = (k0 + 32 < FIN);
        if (more) gload(k0 + 32);      // overlaps with compute below
#pragma unroll
        for (int kk = 0; kk < 32; kk += 8) {
            float a[2][4];
#pragma unroll
            for (int mt = 0; mt < 2; mt++) {
                int r = mw + mt * 16;
                a[mt][0] = As[r + gid][kk + tig];
                a[mt][1] = As[r + gid + 8][kk + tig];
                a[mt][2] = As[r + gid][kk + tig + 4];
                a[mt][3] = As[r + gid + 8][kk + tig + 4];
            }
            float b[4][2];
#pragma unroll
            for (int nt = 0; nt < 4; nt++) {
                b[nt][0] = Bs[kk + tig][nw + nt * 8 + gid];
                b[nt][1] = Bs[kk + tig + 4][nw + nt * 8 + gid];
            }
#pragma unroll
            for (int mt = 0; mt < 2; mt++)
#pragma unroll
                for (int nt = 0; nt < 4; nt++)
                    mma_tf32(acc[mt][nt], a[mt], b[nt]);
        }
        __syncthreads();
        if (more) {
            sstore();
            __syncthreads();
        }
    }

    // ---- epilogue: fp16 h1 + fused per-head attention logits ----
#pragma unroll
    for (int mt = 0; mt < 2; mt++) {
#pragma unroll
        for (int nt = 0; nt < 4; nt++) {
            int r0 = block_row + mw + mt * 16 + gid;
            int c = nw + nt * 8 + 2 * tig;
            int l = (nw + nt * 8) >> 3;          // head for this nt tile
            float as0 = __ldg(a1s + l * 8 + 2 * tig);
            float as1 = __ldg(a1s + l * 8 + 2 * tig + 1);
            float ad0 = __ldg(a1d + l * 8 + 2 * tig);
            float ad1 = __ldg(a1d + l * 8 + 2 * tig + 1);

            float vs  = acc[mt][nt][0] * as0 + acc[mt][nt][1] * as1;   // row r0
            float vd  = acc[mt][nt][0] * ad0 + acc[mt][nt][1] * ad1;
            float vs2 = acc[mt][nt][2] * as0 + acc[mt][nt][3] * as1;   // row r0+8
            float vd2 = acc[mt][nt][2] * ad0 + acc[mt][nt][3] * ad1;
#pragma unroll
            for (int off = 1; off <= 2; off <<= 1) {
                vs  += __shfl_xor_sync(0xffffffffu, vs,  off);
                vd  += __shfl_xor_sync(0xffffffffu, vd,  off);
                vs2 += __shfl_xor_sync(0xffffffffu, vs2, off);
                vd2 += __shfl_xor_sync(0xffffffffu, vd2, off);
            }

            if (r0 < N_NODES) {
                *(__half2*)(g_h1h + (size_t)r0 * 64 + c) =
                    __floats2half2_rn(acc[mt][nt][0], acc[mt][nt][1]);
                if (tig == 0) {
                    g_al1s[r0 * 8 + l] = vs;
                    g_al1d[r0 * 8 + l] = vd;
                }
            }
            if (r0 + 8 < N_NODES) {
                *(__half2*)(g_h1h + (size_t)(r0 + 8) * 64 + c) =
                    __floats2half2_rn(acc[mt][nt][2], acc[mt][nt][3]);
                if (tig == 0) {
                    g_al1s[(r0 + 8) * 8 + l] = vs2;
                    g_al1d[(r0 + 8) * 8 + l] = vd2;
                }
            }
        }
    }
}

// ---------------- edge1 (CSR pull, index prefetch): one warp per dst node ----------------
__global__ __launch_bounds__(256) void edge1_csr_kernel() {
    int w = (blockIdx.x * blockDim.x + threadIdx.x) >> 5;
    if (w >= N_NODES) return;
    const int lane = threadIdx.x & 31;
    const int sub = lane >> 3, l = lane & 7;
    const int i = w;

    float ald = g_al1d[i * 8 + l];
    float acc[8];
#pragma unroll
    for (int j = 0; j < 8; j++) acc[j] = 0.f;
    float wsum = 0.f;

    if (sub == 0) {  // self-loop
        float e = g_al1s[i * 8 + l] + ald;
        float ws = expf(leaky(e));
        wsum = ws;
        uint4 hv = *(const uint4*)(g_h1h + (size_t)i * 64 + l * 8);
        float2 f0 = __half22float2(*(__half2*)&hv.x);
        float2 f1 = __half22float2(*(__half2*)&hv.y);
        float2 f2 = __half22float2(*(__half2*)&hv.z);
        float2 f3 = __half22float2(*(__half2*)&hv.w);
        acc[0] = ws * f0.x; acc[1] = ws * f0.y;
        acc[2] = ws * f1.x; acc[3] = ws * f1.y;
        acc[4] = ws * f2.x; acc[5] = ws * f2.y;
        acc[6] = ws * f3.x; acc[7] = ws * f3.y;
    }

    const int end = g_row_end[i];
    int p = g_row_start[i] + sub;
    int src = (p < end) ? g_csr_src[p] : 0;
    while (p < end) {
        int pn = p + 4;
        int srcn = (pn < end) ? g_csr_src[pn] : 0;   // prefetch next index
        float e = g_al1s[src * 8 + l] + ald;
        float wv = expf(leaky(e));
        wsum += wv;
        uint4 hv = *(const uint4*)(g_h1h + (size_t)src * 64 + l * 8);
        float2 f0 = __half22float2(*(__half2*)&hv.x);
        float2 f1 = __half22float2(*(__half2*)&hv.y);
        float2 f2 = __half22float2(*(__half2*)&hv.z);
        float2 f3 = __half22float2(*(__half2*)&hv.w);
        acc[0] += wv * f0.x; acc[1] += wv * f0.y;
        acc[2] += wv * f1.x; acc[3] += wv * f1.y;
        acc[4] += wv * f2.x; acc[5] += wv * f2.y;
        acc[6] += wv * f3.x; acc[7] += wv * f3.y;
        p = pn;
        src = srcn;
    }

#pragma unroll
    for (int off = 8; off <= 16; off <<= 1) {
        wsum += __shfl_xor_sync(0xffffffffu, wsum, off);
#pragma unroll
        for (int j = 0; j < 8; j++)
            acc[j] += __shfl_xor_sync(0xffffffffu, acc[j], off);
    }

    if (sub == 0) {
        float inv = 1.f / wsum;
        *(float4*)(g_acc1 + (size_t)i * 64 + l * 8) =
            make_float4(acc[0] * inv, acc[1] * inv, acc[2] * inv, acc[3] * inv);
        *(float4*)(g_acc1 + (size_t)i * 64 + l * 8 + 4) =
            make_float4(acc[4] * inv, acc[5] * inv, acc[6] * inv, acc[7] * inv);
    }
}

// ---------------- final1: bias + ELU + GEMM2 + layer-2 attn logits ----------------
__global__ __launch_bounds__(256) void final1_kernel(const float* __restrict__ W2,
                                                     const float* __restrict__ b1,
                                                     const float* __restrict__ a2s,
                                                     const float* __restrict__ a2d) {
    __shared__ float W2s[64 * 16];
    __shared__ float vbuf[16][64];
    const int tid = threadIdx.x;
    for (int j = tid; j < 64 * 16; j += 256) W2s[j] = W2[j];
    __syncthreads();

    int nl = tid >> 4, c = tid & 15;
    int i = blockIdx.x * 16 + nl;

    if (i < N_NODES) {
        float4 a = *(const float4*)(g_acc1 + (size_t)i * 64 + c * 4);
        float4 bb = *(const float4*)(b1 + c * 4);
        float v0 = a.x + bb.x;
        float v1 = a.y + bb.y;
        float v2 = a.z + bb.z;
        float v3 = a.w + bb.w;
        v0 = v0 > 0.f ? v0 : expf(v0) - 1.f;
        v1 = v1 > 0.f ? v1 : expf(v1) - 1.f;
        v2 = v2 > 0.f ? v2 : expf(v2) - 1.f;
        v3 = v3 > 0.f ? v3 : expf(v3) - 1.f;
        vbuf[nl][c * 4 + 0] = v0;
        vbuf[nl][c * 4 + 1] = v1;
        vbuf[nl][c * 4 + 2] = v2;
        vbuf[nl][c * 4 + 3] = v3;
    }
    __syncwarp();

    float h2c = 0.f;
    if (i < N_NODES) {
#pragma unroll
        for (int j = 0; j < 64; j++) h2c += vbuf[nl][j] * W2s[j * 16 + c];
    }
    float als = h2c * a2s[c];
    float ald = h2c * a2d[c];
#pragma unroll
    for (int off = 8; off > 0; off >>= 1) {
        als += __shfl_down_sync(0xffffffffu, als, off, 16);
        ald += __shfl_down_sync(0xffffffffu, ald, off, 16);
    }
    als = __shfl_sync(0xffffffffu, als, 0, 16);
    ald = __shfl_sync(0xffffffffu, ald, 0, 16);

    if (i < N_NODES) {
        g_h2h[i * 16 + c] = __float2half_rn(h2c);
        if (c == 0) {
            g_al2s[i] = als;
            g_al2d[i] = ald;
        }
    }
}

// ---------------- edge2 (CSR pull) + fused bias/log_softmax -> out ----------------
__global__ __launch_bounds__(256) void edge2_csr_kernel(const float* __restrict__ b2,
                                                        float* __restrict__ out) {
    int w = (blockIdx.x * blockDim.x + threadIdx.x) >> 5;
    if (w >= N_NODES) return;
    const int lane = threadIdx.x & 31;
    const int sub = lane >> 2, l = lane & 3;
    const int i = w;

    float ald = g_al2d[i];
    float acc[4];
#pragma unroll
    for (int j = 0; j < 4; j++) acc[j] = 0.f;
    float wsum = 0.f;

    if (sub == 0) {  // self-loop
        float ws = expf(leaky(g_al2s[i] + ald));
        wsum = ws;
        uint2 hv = *(const uint2*)(g_h2h + (size_t)i * 16 + l * 4);
        float2 f0 = __half22float2(*(__half2*)&hv.x);
        float2 f1 = __half22float2(*(__half2*)&hv.y);
        acc[0] = ws * f0.x; acc[1] = ws * f0.y;
        acc[2] = ws * f1.x; acc[3] = ws * f1.y;
    }

    const int end = g_row_end[i];
    int p = g_row_start[i] + sub;
    int src = (p < end) ? g_csr_src[p] : 0;
    while (p < end) {
        int pn = p + 8;
        int srcn = (pn < end) ? g_csr_src[pn] : 0;   // prefetch next index
        float wv = expf(leaky(g_al2s[src] + ald));
        wsum += wv;
        uint2 hv = *(const uint2*)(g_h2h + (size_t)src * 16 + l * 4);
        float2 f0 = __half22float2(*(__half2*)&hv.x);
        float2 f1 = __half22float2(*(__half2*)&hv.y);
        acc[0] += wv * f0.x; acc[1] += wv * f0.y;
        acc[2] += wv * f1.x; acc[3] += wv * f1.y;
        p = pn;
        src = srcn;
    }

#pragma unroll
    for (int off = 4; off <= 16; off <<= 1) {
        wsum += __shfl_xor_sync(0xffffffffu, wsum, off);
#pragma unroll
        for (int j = 0; j < 4; j++)
            acc[j] += __shfl_xor_sync(0xffffffffu, acc[j], off);
    }

    // every lane now holds the reduced sums for its l; finish log_softmax in-warp
    float inv = 1.f / wsum;
    float4 bb = __ldg((const float4*)b2 + l);
    float o0 = acc[0] * inv + bb.x;
    float o1 = acc[1] * inv + bb.y;
    float o2 = acc[2] * inv + bb.z;
    float o3 = acc[3] * inv + bb.w;
    float m = fmaxf(fmaxf(o0, o1), fmaxf(o2, o3));
#pragma unroll
    for (int off = 1; off <= 2; off <<= 1)
        m = fmaxf(m, __shfl_xor_sync(0xffffffffu, m, off, 4));
    float s = expf(o0 - m) + expf(o1 - m) + expf(o2 - m) + expf(o3 - m);
#pragma unroll
    for (int off = 1; off <= 2; off <<= 1)
        s += __shfl_xor_sync(0xffffffffu, s, off, 4);
    float lg = m + logf(s);

    if (sub == 0)
        *(float4*)(out + (size_t)i * 16 + l * 4) =
            make_float4(o0 - lg, o1 - lg, o2 - lg, o3 - lg);
}

// ---------------- launch ----------------
extern "C" void kernel_launch(void* const* d_in, const int* in_sizes, int n_in,
                              void* d_out, int out_size) {
    const float* x   = (const float*)d_in[0];
    const void*  ei  = d_in[1];
    const float* W1  = (const float*)d_in[2];
    const float* a1s = (const float*)d_in[3];
    const float* a1d = (const float*)d_in[4];
    const float* b1  = (const float*)d_in[5];
    const float* W2  = (const float*)d_in[6];
    const float* a2s = (const float*)d_in[7];
    const float* a2d = (const float*)d_in[8];
    const float* b2  = (const float*)d_in[9];
    float* out = (float*)d_out;

    detect_zero_kernel<<<(N_NODES + 255) / 256, 256>>>((const int*)ei);
    hist_kernel<<<(E_EDGES + 255) / 256, 256>>>(ei);
    scan1_kernel<<<SCAN_NB, 1024>>>();                 // scan2 fused (last block)
    scan3_kernel<<<(N_NODES + 255) / 256, 256>>>();
    scatter_kernel<<<(E_EDGES + 255) / 256, 256>>>(ei);
    gemm1_kernel<<<(N_NODES + 127) / 128, 256>>>(x, W1, a1s, a1d);
    edge1_csr_kernel<<<(N_NODES * 32 + 255) / 256, 256>>>();
    final1_kernel<<<(N_NODES + 15) / 16, 256>>>(W2, b1, a2s, a2d);
    edge2_csr_kernel<<<(N_NODES * 32 + 255) / 256, 256>>>(b2, out);   // final2 fused
}